// round 3
// baseline (speedup 1.0000x reference)
#include <cuda_runtime.h>
#include <cuda_bf16.h>
#include <stdint.h>

#define NROWS 131072
#define DDIM  64
#define KPROT 512
#define TM    128
#define TN    64

// ---- shared memory layout (bytes) ----
#define OFF_W2    0       // 64 floats  ||w||^2 per local proto row
#define OFF_INV   256     // 128 floats 1/||x|| per local row
#define OFF_AHI   1024    // 16KB  A hi (128 rows x 128B, swizzled)
#define OFF_ALO   17408   // 16KB  A lo
#define OFF_BHI   33792   // 8KB   B hi (64 rows x 128B)
#define OFF_BLO   41984   // 8KB   B lo
#define OFF_STAGE 50176   // 32KB  fp32 staging tile (<=128 x 64)
#define SMEM_TOTAL (OFF_STAGE + TM*DDIM*4)   // 82944
#define OFF_PBUF  1024    // reuse operand region: 128*68*4 = 34816B
#define PB_STRIDE 68

#define XN1_OFF   ((size_t)NROWS*DDIM)              // 8388608
#define PROTO_OFF ((size_t)2*NROWS*DDIM)            // 16777216
#define SCAL_OFF  (PROTO_OFF + (size_t)NROWS*KPROT) // 83886080

__device__ int   g_rowmin[NROWS];
__device__ int   g_colmin[KPROT];
__device__ float g_partial[128];

// ---------------- helpers ----------------
static __device__ __forceinline__ uint32_t smem_u32(const void* p) {
    uint32_t a;
    asm("{ .reg .u64 t; cvta.to.shared.u64 t, %1; cvt.u32.u64 %0, t; }"
        : "=r"(a) : "l"(p));
    return a;
}
static __device__ __forceinline__ uint32_t swz(uint32_t o) {
    return o ^ ((o >> 3) & 0x70u);
}
static __device__ __forceinline__ void ldsm_x4(uint32_t& r0, uint32_t& r1, uint32_t& r2, uint32_t& r3, uint32_t addr) {
    asm volatile("ldmatrix.sync.aligned.m8n8.x4.shared.b16 {%0,%1,%2,%3}, [%4];"
                 : "=r"(r0), "=r"(r1), "=r"(r2), "=r"(r3) : "r"(addr));
}
static __device__ __forceinline__ void ldsm_x2(uint32_t& r0, uint32_t& r1, uint32_t addr) {
    asm volatile("ldmatrix.sync.aligned.m8n8.x2.shared.b16 {%0,%1}, [%2];"
                 : "=r"(r0), "=r"(r1) : "r"(addr));
}
static __device__ __forceinline__ void mma16816(float& c0, float& c1, float& c2, float& c3,
                                                uint32_t a0, uint32_t a1, uint32_t a2, uint32_t a3,
                                                uint32_t b0, uint32_t b1) {
    asm volatile("mma.sync.aligned.m16n8k16.row.col.f32.bf16.bf16.f32 "
                 "{%0,%1,%2,%3}, {%4,%5,%6,%7}, {%8,%9}, {%0,%1,%2,%3};"
                 : "+f"(c0), "+f"(c1), "+f"(c2), "+f"(c3)
                 : "r"(a0), "r"(a1), "r"(a2), "r"(a3), "r"(b0), "r"(b1));
}

// -------- stage an nrows x 64 fp32 tile (coalesced float4) --------
static __device__ __forceinline__ void load_stage(char* smem, const float* __restrict__ src,
                                                  int tid, int nrows) {
    float4* st = (float4*)(smem + OFF_STAGE);
    const float4* g = (const float4*)src;
    int n4 = nrows * 16;              // float4 count
    for (int i = tid; i < n4; i += 256) st[i] = g[i];
}

// -------- per-row norm + hi/lo bf16 split into swizzled SMEM --------
static __device__ __forceinline__ void convert_tile(char* smem, int wid, int lane,
                                                    uint32_t off_hi, uint32_t off_lo,
                                                    int rows_per_warp, bool do_norm) {
    float* stage = (float*)(smem + OFF_STAGE);
    float* invs  = (float*)(smem + OFF_INV);
    float* w2s   = (float*)(smem + OFF_W2);
#pragma unroll 4
    for (int r = 0; r < rows_per_warp; r++) {
        int row = wid * rows_per_warp + r;
        float2 v = *(const float2*)(stage + row * DDIM + 2 * lane);
        float ss = v.x * v.x + v.y * v.y;
        ss += __shfl_xor_sync(0xFFFFFFFFu, ss, 16);
        ss += __shfl_xor_sync(0xFFFFFFFFu, ss, 8);
        ss += __shfl_xor_sync(0xFFFFFFFFu, ss, 4);
        ss += __shfl_xor_sync(0xFFFFFFFFu, ss, 2);
        ss += __shfl_xor_sync(0xFFFFFFFFu, ss, 1);
        float scale = 1.0f;
        if (do_norm) {
            scale = 1.0f / fmaxf(sqrtf(ss), 1e-12f);
            if (lane == 0) invs[row] = scale;
        } else {
            if (lane == 0) w2s[row] = ss;
        }
        float a0 = v.x * scale, a1 = v.y * scale;
        __nv_bfloat16 h0 = __float2bfloat16(a0);
        __nv_bfloat16 h1 = __float2bfloat16(a1);
        __nv_bfloat16 l0 = __float2bfloat16(a0 - __bfloat162float(h0));
        __nv_bfloat16 l1 = __float2bfloat16(a1 - __bfloat162float(h1));
        uint32_t hp = (uint32_t)__bfloat16_as_ushort(h0) | ((uint32_t)__bfloat16_as_ushort(h1) << 16);
        uint32_t lp = (uint32_t)__bfloat16_as_ushort(l0) | ((uint32_t)__bfloat16_as_ushort(l1) << 16);
        uint32_t sw = swz((uint32_t)(row * 128 + lane * 4));
        *(uint32_t*)(smem + off_hi + sw) = hp;
        *(uint32_t*)(smem + off_lo + sw) = lp;
    }
}

// ---------------- init scratch ----------------
__global__ void init_kernel() {
    int i = blockIdx.x * blockDim.x + threadIdx.x;
    if (i < NROWS) g_rowmin[i] = 0x7F800000;   // +inf
    if (i < KPROT) g_colmin[i] = 0x7F800000;
}

// ---------------- fused normalize + split-bf16 GEMM + distance-min ----------------
__global__ void __launch_bounds__(256, 2)
fused_kernel(const float* __restrict__ x, const float* __restrict__ W,
             float* __restrict__ out) {
    extern __shared__ char smem[];
    const int tid  = threadIdx.x;
    const int wid  = tid >> 5;
    const int lane = tid & 31;
    const int ntile = blockIdx.x;        // 0..7 (fast dim -> L2 reuse of x tile)
    const int mtile = blockIdx.y;        // 0..1023
    const int m0 = mtile * TM;
    const int n0 = ntile * TN;
    const uint32_t sb = smem_u32(smem);

    // ---- stage x tile, normalize, split to bf16 hi/lo ----
    load_stage(smem, x + (size_t)m0 * DDIM, tid, TM);
    __syncthreads();
    convert_tile(smem, wid, lane, OFF_AHI, OFF_ALO, 16, true);
    __syncthreads();

    // ---- write xn twice (only ntile==0 CTAs), coalesced float4 ----
    if (ntile == 0) {
        const float4* stage = (const float4*)(smem + OFF_STAGE);
        const float*  invs  = (const float*)(smem + OFF_INV);
        float4* o0 = (float4*)(out + (size_t)m0 * DDIM);
        float4* o1 = (float4*)(out + XN1_OFF + (size_t)m0 * DDIM);
#pragma unroll
        for (int i = 0; i < 8; i++) {
            int idx = tid + i * 256;     // 0..2047 float4s
            int row = idx >> 4;
            float s = invs[row];
            float4 v = stage[idx];
            v.x *= s; v.y *= s; v.z *= s; v.w *= s;
            o0[idx] = v;
            o1[idx] = v;
        }
    }
    __syncthreads();

    // ---- stage W tile (64 rows), split to bf16 hi/lo (+ ||w||^2) ----
    load_stage(smem, W + (size_t)n0 * DDIM, tid, TN);
    __syncthreads();
    convert_tile(smem, wid, lane, OFF_BHI, OFF_BLO, 8, false);
    __syncthreads();

    // ---- warp-tiled MMA: warp grid 2(M) x 4(N), warp tile 64x16 ----
    const int wm = wid >> 2;             // 0..1
    const int wn = wid & 3;              // 0..3

    float acc[4][2][4];
#pragma unroll
    for (int mb = 0; mb < 4; mb++)
#pragma unroll
        for (int nf = 0; nf < 2; nf++)
#pragma unroll
            for (int c = 0; c < 4; c++) acc[mb][nf][c] = 0.0f;

    // per-lane address components
    const uint32_t a_row = (uint32_t)(wm * 64 + (lane & 7) + ((lane >> 3) & 1) * 8);
    const uint32_t a_kb  = (uint32_t)(((lane >> 4) & 1) * 16);
    const uint32_t b_row0 = (uint32_t)(wn * 16 + (lane & 7));
    const uint32_t b_kb  = (uint32_t)(((lane >> 3) & 1) * 16);

    const uint32_t baseA[3] = {sb + OFF_AHI, sb + OFF_AHI, sb + OFF_ALO};
    const uint32_t baseB[3] = {sb + OFF_BHI, sb + OFF_BLO, sb + OFF_BHI};

#pragma unroll
    for (int p = 0; p < 3; p++) {
        const uint32_t bA = baseA[p];
        const uint32_t bB = baseB[p];
#pragma unroll
        for (int ks = 0; ks < 4; ks++) {
            uint32_t b0[2], b1[2];
#pragma unroll
            for (int nf = 0; nf < 2; nf++) {
                uint32_t addr = bB + swz(((b_row0 + nf * 8) << 7) + (uint32_t)(ks * 32) + b_kb);
                ldsm_x2(b0[nf], b1[nf], addr);
            }
#pragma unroll
            for (int mb = 0; mb < 4; mb++) {
                uint32_t a0, a1, a2, a3;
                uint32_t addr = bA + swz(((a_row + mb * 16) << 7) + (uint32_t)(ks * 32) + a_kb);
                ldsm_x4(a0, a1, a2, a3, addr);
#pragma unroll
                for (int nf = 0; nf < 2; nf++)
                    mma16816(acc[mb][nf][0], acc[mb][nf][1], acc[mb][nf][2], acc[mb][nf][3],
                             a0, a1, a2, a3, b0[nf], b1[nf]);
            }
        }
    }

    __syncthreads();   // operand SMEM dead -> reuse as pbuf

    // ---- write accumulators to SMEM transpose buffer ----
    {
        float* pbuf = (float*)(smem + OFF_PBUF);
        const int rr = lane >> 2;            // 0..7
        const int cc = (lane & 3) * 2;       // 0..6
#pragma unroll
        for (int mb = 0; mb < 4; mb++) {
            int r0 = wm * 64 + mb * 16 + rr;
#pragma unroll
            for (int nf = 0; nf < 2; nf++) {
                int col = wn * 16 + nf * 8 + cc;
                *(float2*)(pbuf + r0 * PB_STRIDE + col)       = make_float2(acc[mb][nf][0], acc[mb][nf][1]);
                *(float2*)(pbuf + (r0 + 8) * PB_STRIDE + col) = make_float2(acc[mb][nf][2], acc[mb][nf][3]);
            }
        }
    }
    __syncthreads();

    // ---- coalesced proto_out store (float4) ----
    {
        const float* pbuf = (const float*)(smem + OFF_PBUF);
        float* po = out + PROTO_OFF + (size_t)m0 * KPROT + n0;
#pragma unroll
        for (int i = 0; i < 8; i++) {
            int idx = tid + i * 256;         // 0..2047 float4s
            int row = idx >> 4;              // 16 float4 per 64-col row
            int c4  = (idx & 15) * 4;
            *(float4*)(po + (size_t)row * KPROT + c4) = *(const float4*)(pbuf + row * PB_STRIDE + c4);
        }
    }

    // ---- row-min: thread pair per row ----
    {
        const float* pbuf = (const float*)(smem + OFF_PBUF);
        const float* w2s  = (const float*)(smem + OFF_W2);
        int row  = tid >> 1;
        int half = tid & 1;
        float rmin = __int_as_float(0x7F800000);
#pragma unroll 8
        for (int c = 0; c < 32; c++) {
            int col = half * 32 + c;
            float sq = fmaf(-2.0f, pbuf[row * PB_STRIDE + col], 1.0f + w2s[col]);
            rmin = fminf(rmin, sq);
        }
        rmin = fminf(rmin, __shfl_xor_sync(0xFFFFFFFFu, rmin, 1));
        if (half == 0)
            atomicMin(&g_rowmin[m0 + row], __float_as_int(fmaxf(rmin, 1e-12f)));
    }

    // ---- column-min: threads 0..63 scan one column each ----
    if (tid < 64) {
        const float* pbuf = (const float*)(smem + OFF_PBUF);
        const float* w2s  = (const float*)(smem + OFF_W2);
        float c0 = 1.0f + w2s[tid];
        float cmin = __int_as_float(0x7F800000);
#pragma unroll 8
        for (int r = 0; r < 128; r++)
            cmin = fminf(cmin, fmaf(-2.0f, pbuf[r * PB_STRIDE + tid], c0));
        atomicMin(&g_colmin[n0 + tid], __float_as_int(fmaxf(cmin, 1e-12f)));
    }
}

// ---------------- deterministic reduction: stage 1 (row mins) ----------------
__global__ void rowred_kernel() {
    __shared__ float red[256];
    int tid = threadIdx.x;
    int base = blockIdx.x * 1024;        // 128 blocks x 1024 rows
    float s = 0.0f;
#pragma unroll
    for (int j = 0; j < 4; j++) {
        int i = base + tid * 4 + j;
        s += sqrtf(fmaxf(__int_as_float(g_rowmin[i]), 1e-12f));
    }
    red[tid] = s;
    __syncthreads();
    for (int st = 128; st > 0; st >>= 1) { if (tid < st) red[tid] += red[tid + st]; __syncthreads(); }
    if (tid == 0) g_partial[blockIdx.x] = red[0];
}

// ---------------- finalize scalars ----------------
__global__ void finalize_kernel(const float* __restrict__ recon,
                                const float* __restrict__ kl,
                                const float* __restrict__ mmd,
                                float* __restrict__ outs) {
    __shared__ float red[256];
    int tid = threadIdx.x;

    float s = (tid < 128) ? g_partial[tid] : 0.0f;
    red[tid] = s;
    __syncthreads();
    for (int st = 128; st > 0; st >>= 1) { if (tid < st) red[tid] += red[tid + st]; __syncthreads(); }
    float rowsum = red[0];
    __syncthreads();

    float c = 0.0f;
#pragma unroll
    for (int j = 0; j < 2; j++) {
        int i = tid * 2 + j;
        c += sqrtf(fmaxf(__int_as_float(g_colmin[i]), 1e-12f));
    }
    red[tid] = c;
    __syncthreads();
    for (int st = 128; st > 0; st >>= 1) { if (tid < st) red[tid] += red[tid + st]; __syncthreads(); }

    if (tid == 0) {
        float colsum = red[0];
        outs[0] = recon[0] + 0.5f * kl[0] + mmd[0];
        outs[1] = 0.5f * (rowsum * (1.0f / (float)NROWS))
                + 0.5f * (colsum * (1.0f / (float)KPROT));
    }
}

extern "C" void kernel_launch(void* const* d_in, const int* in_sizes, int n_in,
                              void* d_out, int out_size) {
    const float* x     = (const float*)d_in[0];
    const float* W     = (const float*)d_in[1];
    const float* recon = (const float*)d_in[2];
    const float* kl    = (const float*)d_in[3];
    const float* mmd   = (const float*)d_in[4];
    float* out = (float*)d_out;
    (void)in_sizes; (void)n_in; (void)out_size;

    cudaFuncSetAttribute(fused_kernel, cudaFuncAttributeMaxDynamicSharedMemorySize, SMEM_TOTAL);

    init_kernel<<<(NROWS + 255) / 256, 256>>>();
    dim3 grid(KPROT / TN, NROWS / TM);
    fused_kernel<<<grid, 256, SMEM_TOTAL>>>(x, W, out);
    rowred_kernel<<<128, 256>>>();
    finalize_kernel<<<1, 256>>>(recon, kl, mmd, out + SCAL_OFF);
}

// round 6
// speedup vs baseline: 1.7104x; 1.7104x over previous
#include <cuda_runtime.h>
#include <cuda_bf16.h>
#include <stdint.h>

#define NROWS 131072
#define DDIM  64
#define KPROT 512
#define TM    128
#define TN    64
#define NTILES (KPROT / TN)   // 8

// ---- shared memory layout (bytes), all 1KB-aligned ----
#define OFF_AHI   0        // 16KB  A hi (128 rows x 128B, swizzled)
#define OFF_ALO   16384    // 16KB  A lo
#define OFF_WB    32768    // 2 x 16KB W double buffer (hi 8KB + lo 8KB each)
#define OFF_W2    65536    // 512 floats (2KB)
#define OFF_RMIN  67584    // 128 ints
#define OFF_CMIN  68096    // 512 ints (2KB)
#define SMEM_TOTAL 70144

#define XN1_OFF   ((size_t)NROWS*DDIM)              // 8388608
#define PROTO_OFF ((size_t)2*NROWS*DDIM)            // 16777216
#define SCAL_OFF  (PROTO_OFF + (size_t)NROWS*KPROT) // 83886080

__device__ int   g_rowmin[NROWS];
__device__ int   g_colmin[KPROT];
__device__ float g_partial[128];
__device__ float g_w2[KPROT];
__device__ __align__(16) unsigned char g_whi[NTILES * 8192];  // swizzled bf16 tiles
__device__ __align__(16) unsigned char g_wlo[NTILES * 8192];

// ---------------- helpers ----------------
static __device__ __forceinline__ uint32_t smem_u32(const void* p) {
    uint32_t a;
    asm("{ .reg .u64 t; cvta.to.shared.u64 t, %1; cvt.u32.u64 %0, t; }"
        : "=r"(a) : "l"(p));
    return a;
}
static __device__ __forceinline__ uint32_t swz(uint32_t o) {
    return o ^ ((o >> 3) & 0x70u);
}
static __device__ __forceinline__ void ldsm_x4(uint32_t& r0, uint32_t& r1, uint32_t& r2, uint32_t& r3, uint32_t addr) {
    asm volatile("ldmatrix.sync.aligned.m8n8.x4.shared.b16 {%0,%1,%2,%3}, [%4];"
                 : "=r"(r0), "=r"(r1), "=r"(r2), "=r"(r3) : "r"(addr));
}
static __device__ __forceinline__ void ldsm_x2(uint32_t& r0, uint32_t& r1, uint32_t addr) {
    asm volatile("ldmatrix.sync.aligned.m8n8.x2.shared.b16 {%0,%1}, [%2];"
                 : "=r"(r0), "=r"(r1) : "r"(addr));
}
static __device__ __forceinline__ void mma16816(float& c0, float& c1, float& c2, float& c3,
                                                uint32_t a0, uint32_t a1, uint32_t a2, uint32_t a3,
                                                uint32_t b0, uint32_t b1) {
    asm volatile("mma.sync.aligned.m16n8k16.row.col.f32.bf16.bf16.f32 "
                 "{%0,%1,%2,%3}, {%4,%5,%6,%7}, {%8,%9}, {%0,%1,%2,%3};"
                 : "+f"(c0), "+f"(c1), "+f"(c2), "+f"(c3)
                 : "r"(a0), "r"(a1), "r"(a2), "r"(a3), "r"(b0), "r"(b1));
}
static __device__ __forceinline__ void cp16(uint32_t dst, const void* src) {
    asm volatile("cp.async.cg.shared.global [%0], [%1], 16;" :: "r"(dst), "l"(src));
}
static __device__ __forceinline__ void cp_commit() {
    asm volatile("cp.async.commit_group;");
}
template<int N> static __device__ __forceinline__ void cp_wait() {
    asm volatile("cp.async.wait_group %0;" :: "n"(N));
}
static __device__ __forceinline__ float warp_red_sum32(float ss) {
    ss += __shfl_xor_sync(0xFFFFFFFFu, ss, 16);
    ss += __shfl_xor_sync(0xFFFFFFFFu, ss, 8);
    ss += __shfl_xor_sync(0xFFFFFFFFu, ss, 4);
    ss += __shfl_xor_sync(0xFFFFFFFFu, ss, 2);
    ss += __shfl_xor_sync(0xFFFFFFFFu, ss, 1);
    return ss;
}
static __device__ __forceinline__ void split_bf16(float a0, float a1, uint32_t& hp, uint32_t& lp) {
    __nv_bfloat16 h0 = __float2bfloat16(a0);
    __nv_bfloat16 h1 = __float2bfloat16(a1);
    __nv_bfloat16 l0 = __float2bfloat16(a0 - __bfloat162float(h0));
    __nv_bfloat16 l1 = __float2bfloat16(a1 - __bfloat162float(h1));
    hp = (uint32_t)__bfloat16_as_ushort(h0) | ((uint32_t)__bfloat16_as_ushort(h1) << 16);
    lp = (uint32_t)__bfloat16_as_ushort(l0) | ((uint32_t)__bfloat16_as_ushort(l1) << 16);
}

// ---------------- init colmin ----------------
__global__ void init_kernel() {
    int i = blockIdx.x * blockDim.x + threadIdx.x;
    if (i < KPROT) g_colmin[i] = 0x7F800000;
}

// ---------------- W prep: fp32 -> swizzled bf16 hi/lo + ||w||^2 ----------------
__global__ void prep_kernel(const float* __restrict__ W) {
    const int tile = blockIdx.x;             // 0..7
    const int tid = threadIdx.x;
    const int wid = tid >> 5;                // 8 warps x 8 rows
    const int lane = tid & 31;
    float2 v[8];
#pragma unroll
    for (int r = 0; r < 8; r++) {
        int rl = wid * 8 + r;
        v[r] = *(const float2*)(W + (size_t)(tile * TN + rl) * DDIM + 2 * lane);
    }
#pragma unroll
    for (int r = 0; r < 8; r++) {
        int rl = wid * 8 + r;
        float ss = warp_red_sum32(v[r].x * v[r].x + v[r].y * v[r].y);
        if (lane == 0) g_w2[tile * TN + rl] = ss;
        uint32_t hp, lp;
        split_bf16(v[r].x, v[r].y, hp, lp);
        uint32_t off = (uint32_t)tile * 8192u + swz((uint32_t)(rl * 128 + lane * 4));
        *(uint32_t*)(g_whi + off) = hp;
        *(uint32_t*)(g_wlo + off) = lp;
    }
}

// ---------------- fused normalize + split-bf16 GEMM + distance-min ----------------
__global__ void __launch_bounds__(256, 3)
fused_kernel(const float* __restrict__ x, float* __restrict__ out) {
    extern __shared__ char smem[];
    const int tid  = threadIdx.x;
    const int wid  = tid >> 5;
    const int lane = tid & 31;
    const int m0   = blockIdx.x * TM;
    const uint32_t sb = smem_u32(smem);

    int*   rowmin_s = (int*)(smem + OFF_RMIN);
    int*   colmin_s = (int*)(smem + OFF_CMIN);
    float* w2s      = (float*)(smem + OFF_W2);

    // init smem scratch + load w2
    if (tid < 128) rowmin_s[tid] = 0x7F800000;
#pragma unroll
    for (int i = tid; i < KPROT; i += 256) {
        colmin_s[i] = 0x7F800000;
        w2s[i] = g_w2[i];
    }

    // prefetch W tile 0 into buffer 0
    {
        uint32_t dst = sb + OFF_WB + (uint32_t)tid * 16;
        cp16(dst,        g_whi + tid * 16);
        cp16(dst + 4096, g_whi + 4096 + tid * 16);
        cp16(dst + 8192, g_wlo + tid * 16);
        cp16(dst + 12288, g_wlo + 4096 + tid * 16);
        cp_commit();
    }

    // ---- A: load, normalize, write xn twice, split to swizzled bf16 hi/lo ----
    {
        float2 v[16];
        const float* xb = x + (size_t)(m0 + wid * 16) * DDIM + 2 * lane;
#pragma unroll
        for (int r = 0; r < 16; r++) v[r] = *(const float2*)(xb + r * DDIM);
        float* o0 = out + (size_t)(m0 + wid * 16) * DDIM + 2 * lane;
        float* o1 = o0 + XN1_OFF;
#pragma unroll
        for (int r = 0; r < 16; r++) {
            float ss = warp_red_sum32(v[r].x * v[r].x + v[r].y * v[r].y);
            float sc = 1.0f / fmaxf(sqrtf(ss), 1e-12f);
            float a0 = v[r].x * sc, a1 = v[r].y * sc;
            *(float2*)(o0 + r * DDIM) = make_float2(a0, a1);
            *(float2*)(o1 + r * DDIM) = make_float2(a0, a1);
            uint32_t hp, lp;
            split_bf16(a0, a1, hp, lp);
            uint32_t sw = swz((uint32_t)((wid * 16 + r) * 128 + lane * 4));
            *(uint32_t*)(smem + OFF_AHI + sw) = hp;
            *(uint32_t*)(smem + OFF_ALO + sw) = lp;
        }
    }

    // warp layout: 2(M) x 4(N)
    const int wm = wid >> 2;
    const int wn = wid & 3;
    const int rr = lane >> 2;            // acc row within 8
    const int cc = (lane & 3) * 2;       // acc col pair

    // ldmatrix lane address components
    const uint32_t a_row  = (uint32_t)(wm * 64 + (lane & 7) + ((lane >> 3) & 1) * 8);
    const uint32_t a_kb   = (uint32_t)(((lane >> 4) & 1) * 16);
    const uint32_t b_row0 = (uint32_t)(wn * 16 + (lane & 7));
    const uint32_t b_kb   = (uint32_t)(((lane >> 3) & 1) * 16);

    float rm[8];
#pragma unroll
    for (int s = 0; s < 8; s++) rm[s] = __int_as_float(0x7F800000);

    float* proto = out + PROTO_OFF;

    for (int t = 0; t < NTILES; t++) {
        __syncthreads();   // prior tile's ldsm done; safe to overwrite other buffer
        if (t < NTILES - 1) {
            uint32_t dst = sb + OFF_WB + (uint32_t)(((t + 1) & 1) * 16384) + (uint32_t)tid * 16;
            const unsigned char* sh = g_whi + (t + 1) * 8192 + tid * 16;
            const unsigned char* sl = g_wlo + (t + 1) * 8192 + tid * 16;
            cp16(dst, sh); cp16(dst + 4096, sh + 4096);
            cp16(dst + 8192, sl); cp16(dst + 12288, sl + 4096);
            cp_commit();
            cp_wait<1>();
        } else {
            cp_wait<0>();
        }
        __syncthreads();   // W tile t visible

        const uint32_t wb = sb + OFF_WB + (uint32_t)((t & 1) * 16384);

        float acc[4][2][4];
#pragma unroll
        for (int mb = 0; mb < 4; mb++)
#pragma unroll
            for (int nf = 0; nf < 2; nf++)
#pragma unroll
                for (int c = 0; c < 4; c++) acc[mb][nf][c] = 0.0f;

        const uint32_t baseA[3]  = {sb + OFF_AHI, sb + OFF_AHI, sb + OFF_ALO};
        const uint32_t baseB[3]  = {wb, wb + 8192u, wb};
#pragma unroll
        for (int p = 0; p < 3; p++) {
            const uint32_t bA = baseA[p];
            const uint32_t bB = baseB[p];
#pragma unroll
            for (int ks = 0; ks < 4; ks++) {
                uint32_t b0[2], b1[2];
#pragma unroll
                for (int nf = 0; nf < 2; nf++) {
                    uint32_t addr = bB + swz(((b_row0 + nf * 8) << 7) + (uint32_t)(ks * 32) + b_kb);
                    ldsm_x2(b0[nf], b1[nf], addr);
                }
#pragma unroll
                for (int mb = 0; mb < 4; mb++) {
                    uint32_t a0, a1, a2, a3;
                    uint32_t addr = bA + swz(((a_row + mb * 16) << 7) + (uint32_t)(ks * 32) + a_kb);
                    ldsm_x4(a0, a1, a2, a3, addr);
#pragma unroll
                    for (int nf = 0; nf < 2; nf++)
                        mma16816(acc[mb][nf][0], acc[mb][nf][1], acc[mb][nf][2], acc[mb][nf][3],
                                 a0, a1, a2, a3, b0[nf], b1[nf]);
                }
            }
        }

        // ---- proto store directly from accumulators ----
#pragma unroll
        for (int mb = 0; mb < 4; mb++) {
            size_t rowg = (size_t)(m0 + wm * 64 + mb * 16 + rr);
            float* base = proto + rowg * KPROT + t * TN + wn * 16 + cc;
#pragma unroll
            for (int nf = 0; nf < 2; nf++) {
                *(float2*)(base + nf * 8)             = make_float2(acc[mb][nf][0], acc[mb][nf][1]);
                *(float2*)(base + nf * 8 + 8 * KPROT) = make_float2(acc[mb][nf][2], acc[mb][nf][3]);
            }
        }

        // ---- distance mins ----
#pragma unroll
        for (int nf = 0; nf < 2; nf++) {
            int colg = t * TN + wn * 16 + nf * 8 + cc;
            float w0 = 1.0f + w2s[colg];
            float w1 = 1.0f + w2s[colg + 1];
            float cm0 = __int_as_float(0x7F800000);
            float cm1 = cm0;
#pragma unroll
            for (int mb = 0; mb < 4; mb++) {
                float s0 = fmaf(-2.0f, acc[mb][nf][0], w0);
                float s1 = fmaf(-2.0f, acc[mb][nf][1], w1);
                float s2 = fmaf(-2.0f, acc[mb][nf][2], w0);
                float s3 = fmaf(-2.0f, acc[mb][nf][3], w1);
                rm[mb * 2]     = fminf(rm[mb * 2],     fminf(s0, s1));
                rm[mb * 2 + 1] = fminf(rm[mb * 2 + 1], fminf(s2, s3));
                cm0 = fminf(cm0, fminf(s0, s2));
                cm1 = fminf(cm1, fminf(s1, s3));
            }
            cm0 = fminf(cm0, __shfl_xor_sync(0xFFFFFFFFu, cm0, 4));
            cm0 = fminf(cm0, __shfl_xor_sync(0xFFFFFFFFu, cm0, 8));
            cm0 = fminf(cm0, __shfl_xor_sync(0xFFFFFFFFu, cm0, 16));
            cm1 = fminf(cm1, __shfl_xor_sync(0xFFFFFFFFu, cm1, 4));
            cm1 = fminf(cm1, __shfl_xor_sync(0xFFFFFFFFu, cm1, 8));
            cm1 = fminf(cm1, __shfl_xor_sync(0xFFFFFFFFu, cm1, 16));
            if (lane < 4) {
                atomicMin(&colmin_s[colg],     __float_as_int(fmaxf(cm0, 1e-12f)));
                atomicMin(&colmin_s[colg + 1], __float_as_int(fmaxf(cm1, 1e-12f)));
            }
        }
    }

    // ---- finalize row mins (register -> lane reduce -> smem -> global store) ----
#pragma unroll
    for (int s = 0; s < 8; s++) {
        rm[s] = fminf(rm[s], __shfl_xor_sync(0xFFFFFFFFu, rm[s], 1));
        rm[s] = fminf(rm[s], __shfl_xor_sync(0xFFFFFFFFu, rm[s], 2));
    }
    if ((lane & 3) == 0) {
#pragma unroll
        for (int s = 0; s < 8; s++) {
            int rl = wm * 64 + (s >> 1) * 16 + rr + (s & 1) * 8;
            atomicMin(&rowmin_s[rl], __float_as_int(fmaxf(rm[s], 1e-12f)));
        }
    }
    __syncthreads();
    if (tid < 128) g_rowmin[m0 + tid] = rowmin_s[tid];
#pragma unroll
    for (int i = tid; i < KPROT; i += 256)
        atomicMin(&g_colmin[i], colmin_s[i]);
}

// ---------------- deterministic reduction: stage 1 (row mins) ----------------
__global__ void rowred_kernel() {
    __shared__ float red[256];
    int tid = threadIdx.x;
    int base = blockIdx.x * 1024;
    float s = 0.0f;
#pragma unroll
    for (int j = 0; j < 4; j++) {
        int i = base + tid * 4 + j;
        s += sqrtf(fmaxf(__int_as_float(g_rowmin[i]), 1e-12f));
    }
    red[tid] = s;
    __syncthreads();
    for (int st = 128; st > 0; st >>= 1) { if (tid < st) red[tid] += red[tid + st]; __syncthreads(); }
    if (tid == 0) g_partial[blockIdx.x] = red[0];
}

// ---------------- finalize scalars ----------------
__global__ void finalize_kernel(const float* __restrict__ recon,
                                const float* __restrict__ kl,
                                const float* __restrict__ mmd,
                                float* __restrict__ outs) {
    __shared__ float red[256];
    int tid = threadIdx.x;

    float s = (tid < 128) ? g_partial[tid] : 0.0f;
    red[tid] = s;
    __syncthreads();
    for (int st = 128; st > 0; st >>= 1) { if (tid < st) red[tid] += red[tid + st]; __syncthreads(); }
    float rowsum = red[0];
    __syncthreads();

    float c = 0.0f;
#pragma unroll
    for (int j = 0; j < 2; j++) {
        int i = tid * 2 + j;
        c += sqrtf(fmaxf(__int_as_float(g_colmin[i]), 1e-12f));
    }
    red[tid] = c;
    __syncthreads();
    for (int st = 128; st > 0; st >>= 1) { if (tid < st) red[tid] += red[tid + st]; __syncthreads(); }

    if (tid == 0) {
        float colsum = red[0];
        outs[0] = recon[0] + 0.5f * kl[0] + mmd[0];
        outs[1] = 0.5f * (rowsum * (1.0f / (float)NROWS))
                + 0.5f * (colsum * (1.0f / (float)KPROT));
    }
}

extern "C" void kernel_launch(void* const* d_in, const int* in_sizes, int n_in,
                              void* d_out, int out_size) {
    const float* x     = (const float*)d_in[0];
    const float* W     = (const float*)d_in[1];
    const float* recon = (const float*)d_in[2];
    const float* kl    = (const float*)d_in[3];
    const float* mmd   = (const float*)d_in[4];
    float* out = (float*)d_out;
    (void)in_sizes; (void)n_in; (void)out_size;

    cudaFuncSetAttribute(fused_kernel, cudaFuncAttributeMaxDynamicSharedMemorySize, SMEM_TOTAL);

    init_kernel<<<2, 256>>>();
    prep_kernel<<<NTILES, 256>>>(W);
    fused_kernel<<<NROWS / TM, 256, SMEM_TOTAL>>>(x, out);
    rowred_kernel<<<128, 256>>>();
    finalize_kernel<<<1, 256>>>(recon, kl, mmd, out + SCAL_OFF);
}

// round 7
// speedup vs baseline: 2.0277x; 1.1855x over previous
#include <cuda_runtime.h>
#include <cuda_bf16.h>
#include <stdint.h>

#define NROWS 131072
#define DDIM  64
#define KPROT 512
#define TM    128
#define TN    64
#define NTILES (KPROT / TN)   // 8

// ---- shared memory layout (bytes), all 1KB-aligned ----
#define OFF_AHI   0        // 16KB  A hi (128 rows x 128B, swizzled)
#define OFF_ALO   16384    // 16KB  A lo
#define OFF_WB    32768    // 2 x 16KB W double buffer (hi 8KB + lo 8KB each)
#define OFF_W2    65536    // 512 floats (2KB)
#define OFF_RMIN  67584    // 128 ints
#define OFF_CMIN  68096    // 512 ints (2KB)
#define SMEM_TOTAL 70144

#define XN1_OFF   ((size_t)NROWS*DDIM)              // 8388608
#define PROTO_OFF ((size_t)2*NROWS*DDIM)            // 16777216
#define SCAL_OFF  (PROTO_OFF + (size_t)NROWS*KPROT) // 83886080

__device__ int   g_rowmin[NROWS];
__device__ int   g_colmin[KPROT];
__device__ float g_partial[128];
__device__ float g_w2[KPROT];
__device__ __align__(16) unsigned char g_whi[NTILES * 8192];  // swizzled bf16 tiles
__device__ __align__(16) unsigned char g_wlo[NTILES * 8192];

// ---------------- helpers ----------------
static __device__ __forceinline__ uint32_t smem_u32(const void* p) {
    uint32_t a;
    asm("{ .reg .u64 t; cvta.to.shared.u64 t, %1; cvt.u32.u64 %0, t; }"
        : "=r"(a) : "l"(p));
    return a;
}
static __device__ __forceinline__ uint32_t swz(uint32_t o) {
    return o ^ ((o >> 3) & 0x70u);
}
static __device__ __forceinline__ void ldsm_x4(uint32_t& r0, uint32_t& r1, uint32_t& r2, uint32_t& r3, uint32_t addr) {
    asm volatile("ldmatrix.sync.aligned.m8n8.x4.shared.b16 {%0,%1,%2,%3}, [%4];"
                 : "=r"(r0), "=r"(r1), "=r"(r2), "=r"(r3) : "r"(addr));
}
static __device__ __forceinline__ void mma16816(float& c0, float& c1, float& c2, float& c3,
                                                uint32_t a0, uint32_t a1, uint32_t a2, uint32_t a3,
                                                uint32_t b0, uint32_t b1) {
    asm volatile("mma.sync.aligned.m16n8k16.row.col.f32.bf16.bf16.f32 "
                 "{%0,%1,%2,%3}, {%4,%5,%6,%7}, {%8,%9}, {%0,%1,%2,%3};"
                 : "+f"(c0), "+f"(c1), "+f"(c2), "+f"(c3)
                 : "r"(a0), "r"(a1), "r"(a2), "r"(a3), "r"(b0), "r"(b1));
}
static __device__ __forceinline__ void cp16(uint32_t dst, const void* src) {
    asm volatile("cp.async.cg.shared.global [%0], [%1], 16;" :: "r"(dst), "l"(src));
}
static __device__ __forceinline__ void cp_commit() {
    asm volatile("cp.async.commit_group;");
}
template<int N> static __device__ __forceinline__ void cp_wait() {
    asm volatile("cp.async.wait_group %0;" :: "n"(N));
}
static __device__ __forceinline__ float warp_red_sum32(float ss) {
    ss += __shfl_xor_sync(0xFFFFFFFFu, ss, 16);
    ss += __shfl_xor_sync(0xFFFFFFFFu, ss, 8);
    ss += __shfl_xor_sync(0xFFFFFFFFu, ss, 4);
    ss += __shfl_xor_sync(0xFFFFFFFFu, ss, 2);
    ss += __shfl_xor_sync(0xFFFFFFFFu, ss, 1);
    return ss;
}
static __device__ __forceinline__ void split_bf16(float a0, float a1, uint32_t& hp, uint32_t& lp) {
    __nv_bfloat16 h0 = __float2bfloat16(a0);
    __nv_bfloat16 h1 = __float2bfloat16(a1);
    __nv_bfloat16 l0 = __float2bfloat16(a0 - __bfloat162float(h0));
    __nv_bfloat16 l1 = __float2bfloat16(a1 - __bfloat162float(h1));
    hp = (uint32_t)__bfloat16_as_ushort(h0) | ((uint32_t)__bfloat16_as_ushort(h1) << 16);
    lp = (uint32_t)__bfloat16_as_ushort(l0) | ((uint32_t)__bfloat16_as_ushort(l1) << 16);
}

// ---------------- W prep (+ colmin init): fp32 -> swizzled bf16 hi/lo + ||w||^2 ----------------
__global__ void prep_kernel(const float* __restrict__ W) {
    const int tile = blockIdx.x;             // 0..7
    const int tid = threadIdx.x;
    const int wid = tid >> 5;                // 8 warps x 8 rows
    const int lane = tid & 31;
    if (tile == 0) {                          // init colmin (rowmin is plain-stored)
        g_colmin[tid]       = 0x7F800000;
        g_colmin[tid + 256] = 0x7F800000;
    }
    float2 v[8];
#pragma unroll
    for (int r = 0; r < 8; r++) {
        int rl = wid * 8 + r;
        v[r] = *(const float2*)(W + (size_t)(tile * TN + rl) * DDIM + 2 * lane);
    }
#pragma unroll
    for (int r = 0; r < 8; r++) {
        int rl = wid * 8 + r;
        float ss = warp_red_sum32(v[r].x * v[r].x + v[r].y * v[r].y);
        if (lane == 0) g_w2[tile * TN + rl] = ss;
        uint32_t hp, lp;
        split_bf16(v[r].x, v[r].y, hp, lp);
        uint32_t off = (uint32_t)tile * 8192u + swz((uint32_t)(rl * 128 + lane * 4));
        *(uint32_t*)(g_whi + off) = hp;
        *(uint32_t*)(g_wlo + off) = lp;
    }
}

// ---------------- fused normalize + split-bf16 GEMM + distance-min ----------------
__global__ void __launch_bounds__(256, 3)
fused_kernel(const float* __restrict__ x, float* __restrict__ out) {
    extern __shared__ char smem[];
    const int tid  = threadIdx.x;
    const int wid  = tid >> 5;
    const int lane = tid & 31;
    const int m0   = blockIdx.x * TM;
    const uint32_t sb = smem_u32(smem);

    int*   rowmin_s = (int*)(smem + OFF_RMIN);
    int*   colmin_s = (int*)(smem + OFF_CMIN);
    float* w2s      = (float*)(smem + OFF_W2);

    // init smem scratch + load w2
    if (tid < 128) rowmin_s[tid] = 0x7F800000;
#pragma unroll
    for (int i = tid; i < KPROT; i += 256) {
        colmin_s[i] = 0x7F800000;
        w2s[i] = g_w2[i];
    }

    // prefetch W tile 0 into buffer 0
    {
        uint32_t dst = sb + OFF_WB + (uint32_t)tid * 16;
        cp16(dst,         g_whi + tid * 16);
        cp16(dst + 4096,  g_whi + 4096 + tid * 16);
        cp16(dst + 8192,  g_wlo + tid * 16);
        cp16(dst + 12288, g_wlo + 4096 + tid * 16);
        cp_commit();
    }

    // ---- A: load, normalize, write xn twice, split to swizzled bf16 hi/lo ----
    {
        float2 v[16];
        const float* xb = x + (size_t)(m0 + wid * 16) * DDIM + 2 * lane;
#pragma unroll
        for (int r = 0; r < 16; r++) v[r] = *(const float2*)(xb + r * DDIM);
        float* o0 = out + (size_t)(m0 + wid * 16) * DDIM + 2 * lane;
        float* o1 = o0 + XN1_OFF;
#pragma unroll
        for (int r = 0; r < 16; r++) {
            float ss = warp_red_sum32(v[r].x * v[r].x + v[r].y * v[r].y);
            float sc = 1.0f / fmaxf(sqrtf(ss), 1e-12f);
            float a0 = v[r].x * sc, a1 = v[r].y * sc;
            *(float2*)(o0 + r * DDIM) = make_float2(a0, a1);
            *(float2*)(o1 + r * DDIM) = make_float2(a0, a1);
            uint32_t hp, lp;
            split_bf16(a0, a1, hp, lp);
            uint32_t sw = swz((uint32_t)((wid * 16 + r) * 128 + lane * 4));
            *(uint32_t*)(smem + OFF_AHI + sw) = hp;
            *(uint32_t*)(smem + OFF_ALO + sw) = lp;
        }
    }

    // warp layout: 4(M) x 2(N); warp tile 32(M) x 32(N)
    const int wm = wid & 3;              // 0..3 -> M rows [wm*32, +32)
    const int wn = wid >> 2;             // 0..1 -> N cols [wn*32, +32)
    const int rr = lane >> 2;            // acc row within 8
    const int cc = (lane & 3) * 2;       // acc col pair

    // ldmatrix lane address components (x4 for both A and B)
    const uint32_t a_row  = (uint32_t)(wm * 32 + (lane & 7) + ((lane >> 3) & 1) * 8);
    const uint32_t a_kb   = (uint32_t)(((lane >> 4) & 1) * 16);
    const uint32_t b_row  = (uint32_t)(wn * 32 + (lane & 7) + ((lane >> 4) & 1) * 8);
    const uint32_t b_kb   = (uint32_t)(((lane >> 3) & 1) * 16);

    float rm[4];
#pragma unroll
    for (int s = 0; s < 4; s++) rm[s] = __int_as_float(0x7F800000);

    float* proto = out + PROTO_OFF;

    for (int t = 0; t < NTILES; t++) {
        __syncthreads();   // prior tile's ldsm done; safe to overwrite other buffer
        if (t < NTILES - 1) {
            uint32_t dst = sb + OFF_WB + (uint32_t)(((t + 1) & 1) * 16384) + (uint32_t)tid * 16;
            const unsigned char* sh = g_whi + (t + 1) * 8192 + tid * 16;
            const unsigned char* sl = g_wlo + (t + 1) * 8192 + tid * 16;
            cp16(dst, sh); cp16(dst + 4096, sh + 4096);
            cp16(dst + 8192, sl); cp16(dst + 12288, sl + 4096);
            cp_commit();
            cp_wait<1>();
        } else {
            cp_wait<0>();
        }
        __syncthreads();   // W tile t visible

        const uint32_t wb = sb + OFF_WB + (uint32_t)((t & 1) * 16384);

        float acc[2][4][4];
#pragma unroll
        for (int mb = 0; mb < 2; mb++)
#pragma unroll
            for (int nf = 0; nf < 4; nf++)
#pragma unroll
                for (int c = 0; c < 4; c++) acc[mb][nf][c] = 0.0f;

        const uint32_t baseA[3]  = {sb + OFF_AHI, sb + OFF_AHI, sb + OFF_ALO};
        const uint32_t baseB[3]  = {wb, wb + 8192u, wb};
#pragma unroll
        for (int p = 0; p < 3; p++) {
            const uint32_t bA = baseA[p];
            const uint32_t bB = baseB[p];
#pragma unroll
            for (int ks = 0; ks < 4; ks++) {
                // B: 2 x ldsm_x4, each covers n16 x k16
                uint32_t bf[2][4];
#pragma unroll
                for (int nb = 0; nb < 2; nb++) {
                    uint32_t addr = bB + swz(((b_row + nb * 16) << 7) + (uint32_t)(ks * 32) + b_kb);
                    ldsm_x4(bf[nb][0], bf[nb][1], bf[nb][2], bf[nb][3], addr);
                }
#pragma unroll
                for (int mb = 0; mb < 2; mb++) {
                    uint32_t a0, a1, a2, a3;
                    uint32_t addr = bA + swz(((a_row + mb * 16) << 7) + (uint32_t)(ks * 32) + a_kb);
                    ldsm_x4(a0, a1, a2, a3, addr);
#pragma unroll
                    for (int nb = 0; nb < 2; nb++) {
                        mma16816(acc[mb][nb*2][0],   acc[mb][nb*2][1],   acc[mb][nb*2][2],   acc[mb][nb*2][3],
                                 a0, a1, a2, a3, bf[nb][0], bf[nb][1]);
                        mma16816(acc[mb][nb*2+1][0], acc[mb][nb*2+1][1], acc[mb][nb*2+1][2], acc[mb][nb*2+1][3],
                                 a0, a1, a2, a3, bf[nb][2], bf[nb][3]);
                    }
                }
            }
        }

        // ---- proto store directly from accumulators ----
#pragma unroll
        for (int mb = 0; mb < 2; mb++) {
            size_t rowg = (size_t)(m0 + wm * 32 + mb * 16 + rr);
            float* base = proto + rowg * KPROT + t * TN + wn * 32 + cc;
#pragma unroll
            for (int nf = 0; nf < 4; nf++) {
                *(float2*)(base + nf * 8)             = make_float2(acc[mb][nf][0], acc[mb][nf][1]);
                *(float2*)(base + nf * 8 + 8 * KPROT) = make_float2(acc[mb][nf][2], acc[mb][nf][3]);
            }
        }

        // ---- distance mins ----
#pragma unroll
        for (int nf = 0; nf < 4; nf++) {
            int colg = t * TN + wn * 32 + nf * 8 + cc;
            float w0 = 1.0f + w2s[colg];
            float w1 = 1.0f + w2s[colg + 1];
            float cm0 = __int_as_float(0x7F800000);
            float cm1 = cm0;
#pragma unroll
            for (int mb = 0; mb < 2; mb++) {
                float s0 = fmaf(-2.0f, acc[mb][nf][0], w0);
                float s1 = fmaf(-2.0f, acc[mb][nf][1], w1);
                float s2 = fmaf(-2.0f, acc[mb][nf][2], w0);
                float s3 = fmaf(-2.0f, acc[mb][nf][3], w1);
                rm[mb * 2]     = fminf(rm[mb * 2],     fminf(s0, s1));
                rm[mb * 2 + 1] = fminf(rm[mb * 2 + 1], fminf(s2, s3));
                cm0 = fminf(cm0, fminf(s0, s2));
                cm1 = fminf(cm1, fminf(s1, s3));
            }
            cm0 = fminf(cm0, __shfl_xor_sync(0xFFFFFFFFu, cm0, 4));
            cm0 = fminf(cm0, __shfl_xor_sync(0xFFFFFFFFu, cm0, 8));
            cm0 = fminf(cm0, __shfl_xor_sync(0xFFFFFFFFu, cm0, 16));
            cm1 = fminf(cm1, __shfl_xor_sync(0xFFFFFFFFu, cm1, 4));
            cm1 = fminf(cm1, __shfl_xor_sync(0xFFFFFFFFu, cm1, 8));
            cm1 = fminf(cm1, __shfl_xor_sync(0xFFFFFFFFu, cm1, 16));
            if (lane < 4) {
                atomicMin(&colmin_s[colg],     __float_as_int(fmaxf(cm0, 1e-12f)));
                atomicMin(&colmin_s[colg + 1], __float_as_int(fmaxf(cm1, 1e-12f)));
            }
        }
    }

    // ---- finalize row mins (register -> lane reduce -> smem -> global store) ----
#pragma unroll
    for (int s = 0; s < 4; s++) {
        rm[s] = fminf(rm[s], __shfl_xor_sync(0xFFFFFFFFu, rm[s], 1));
        rm[s] = fminf(rm[s], __shfl_xor_sync(0xFFFFFFFFu, rm[s], 2));
    }
    if ((lane & 3) == 0) {
#pragma unroll
        for (int s = 0; s < 4; s++) {
            int rl = wm * 32 + (s >> 1) * 16 + rr + (s & 1) * 8;
            atomicMin(&rowmin_s[rl], __float_as_int(fmaxf(rm[s], 1e-12f)));
        }
    }
    __syncthreads();
    if (tid < 128) g_rowmin[m0 + tid] = rowmin_s[tid];
#pragma unroll
    for (int i = tid; i < KPROT; i += 256)
        atomicMin(&g_colmin[i], colmin_s[i]);
}

// ---------------- deterministic reduction: stage 1 (row mins) ----------------
__global__ void rowred_kernel() {
    __shared__ float red[256];
    int tid = threadIdx.x;
    int base = blockIdx.x * 1024;
    float s = 0.0f;
#pragma unroll
    for (int j = 0; j < 4; j++) {
        int i = base + tid * 4 + j;
        s += sqrtf(fmaxf(__int_as_float(g_rowmin[i]), 1e-12f));
    }
    red[tid] = s;
    __syncthreads();
    for (int st = 128; st > 0; st >>= 1) { if (tid < st) red[tid] += red[tid + st]; __syncthreads(); }
    if (tid == 0) g_partial[blockIdx.x] = red[0];
}

// ---------------- finalize scalars ----------------
__global__ void finalize_kernel(const float* __restrict__ recon,
                                const float* __restrict__ kl,
                                const float* __restrict__ mmd,
                                float* __restrict__ outs) {
    __shared__ float red[256];
    int tid = threadIdx.x;

    float s = (tid < 128) ? g_partial[tid] : 0.0f;
    red[tid] = s;
    __syncthreads();
    for (int st = 128; st > 0; st >>= 1) { if (tid < st) red[tid] += red[tid + st]; __syncthreads(); }
    float rowsum = red[0];
    __syncthreads();

    float c = 0.0f;
#pragma unroll
    for (int j = 0; j < 2; j++) {
        int i = tid * 2 + j;
        c += sqrtf(fmaxf(__int_as_float(g_colmin[i]), 1e-12f));
    }
    red[tid] = c;
    __syncthreads();
    for (int st = 128; st > 0; st >>= 1) { if (tid < st) red[tid] += red[tid + st]; __syncthreads(); }

    if (tid == 0) {
        float colsum = red[0];
        outs[0] = recon[0] + 0.5f * kl[0] + mmd[0];
        outs[1] = 0.5f * (rowsum * (1.0f / (float)NROWS))
                + 0.5f * (colsum * (1.0f / (float)KPROT));
    }
}

extern "C" void kernel_launch(void* const* d_in, const int* in_sizes, int n_in,
                              void* d_out, int out_size) {
    const float* x     = (const float*)d_in[0];
    const float* W     = (const float*)d_in[1];
    const float* recon = (const float*)d_in[2];
    const float* kl    = (const float*)d_in[3];
    const float* mmd   = (const float*)d_in[4];
    float* out = (float*)d_out;
    (void)in_sizes; (void)n_in; (void)out_size;

    cudaFuncSetAttribute(fused_kernel, cudaFuncAttributeMaxDynamicSharedMemorySize, SMEM_TOTAL);

    prep_kernel<<<NTILES, 256>>>(W);
    fused_kernel<<<NROWS / TM, 256, SMEM_TOTAL>>>(x, out);
    rowred_kernel<<<128, 256>>>();
    finalize_kernel<<<1, 256>>>(recon, kl, mmd, out + SCAL_OFF);
}

// round 8
// speedup vs baseline: 3.5529x; 1.7522x over previous
#include <cuda_runtime.h>
#include <cuda_bf16.h>
#include <stdint.h>

#define NROWS 131072
#define DDIM  64
#define KPROT 512
#define TM    128
#define TN    64
#define NTILES (KPROT / TN)   // 8

// ---- shared memory layout (bytes), all 1KB-aligned ----
#define OFF_AHI   0        // 16KB  A hi (128 rows x 128B, swizzled)
#define OFF_ALO   16384    // 16KB  A lo
#define OFF_WB    32768    // 2 x 16KB W double buffer (hi 8KB + lo 8KB each)
#define OFF_W2    65536    // 512 floats (2KB)
#define OFF_RMIN  67584    // 128 ints
#define OFF_CMIN  68096    // 512 ints (2KB)
#define SMEM_TOTAL 70144

#define XN1_OFF   ((size_t)NROWS*DDIM)              // 8388608
#define PROTO_OFF ((size_t)2*NROWS*DDIM)            // 16777216
#define SCAL_OFF  (PROTO_OFF + (size_t)NROWS*KPROT) // 83886080

__device__ int   g_rowmin[NROWS];
__device__ int   g_colmin[KPROT];
__device__ float g_partial[128];
__device__ float g_w2[KPROT];
__device__ __align__(16) unsigned char g_whi[NTILES * 8192];  // swizzled bf16 tiles
__device__ __align__(16) unsigned char g_wlo[NTILES * 8192];

// ---------------- helpers ----------------
static __device__ __forceinline__ uint32_t smem_u32(const void* p) {
    uint32_t a;
    asm("{ .reg .u64 t; cvta.to.shared.u64 t, %1; cvt.u32.u64 %0, t; }"
        : "=r"(a) : "l"(p));
    return a;
}
static __device__ __forceinline__ uint32_t swz(uint32_t o) {
    return o ^ ((o >> 3) & 0x70u);
}
static __device__ __forceinline__ void ldsm_x4(uint32_t& r0, uint32_t& r1, uint32_t& r2, uint32_t& r3, uint32_t addr) {
    asm volatile("ldmatrix.sync.aligned.m8n8.x4.shared.b16 {%0,%1,%2,%3}, [%4];"
                 : "=r"(r0), "=r"(r1), "=r"(r2), "=r"(r3) : "r"(addr));
}
static __device__ __forceinline__ void mma16816(float& c0, float& c1, float& c2, float& c3,
                                                uint32_t a0, uint32_t a1, uint32_t a2, uint32_t a3,
                                                uint32_t b0, uint32_t b1) {
    asm volatile("mma.sync.aligned.m16n8k16.row.col.f32.bf16.bf16.f32 "
                 "{%0,%1,%2,%3}, {%4,%5,%6,%7}, {%8,%9}, {%0,%1,%2,%3};"
                 : "+f"(c0), "+f"(c1), "+f"(c2), "+f"(c3)
                 : "r"(a0), "r"(a1), "r"(a2), "r"(a3), "r"(b0), "r"(b1));
}
static __device__ __forceinline__ void cp16(uint32_t dst, const void* src) {
    asm volatile("cp.async.cg.shared.global [%0], [%1], 16;" :: "r"(dst), "l"(src));
}
static __device__ __forceinline__ void cp_commit() {
    asm volatile("cp.async.commit_group;");
}
template<int N> static __device__ __forceinline__ void cp_wait() {
    asm volatile("cp.async.wait_group %0;" :: "n"(N));
}
static __device__ __forceinline__ float warp_red_sum32(float ss) {
    ss += __shfl_xor_sync(0xFFFFFFFFu, ss, 16);
    ss += __shfl_xor_sync(0xFFFFFFFFu, ss, 8);
    ss += __shfl_xor_sync(0xFFFFFFFFu, ss, 4);
    ss += __shfl_xor_sync(0xFFFFFFFFu, ss, 2);
    ss += __shfl_xor_sync(0xFFFFFFFFu, ss, 1);
    return ss;
}
static __device__ __forceinline__ void split_bf16(float a0, float a1, uint32_t& hp, uint32_t& lp) {
    __nv_bfloat16 h0 = __float2bfloat16(a0);
    __nv_bfloat16 h1 = __float2bfloat16(a1);
    __nv_bfloat16 l0 = __float2bfloat16(a0 - __bfloat162float(h0));
    __nv_bfloat16 l1 = __float2bfloat16(a1 - __bfloat162float(h1));
    hp = (uint32_t)__bfloat16_as_ushort(h0) | ((uint32_t)__bfloat16_as_ushort(h1) << 16);
    lp = (uint32_t)__bfloat16_as_ushort(l0) | ((uint32_t)__bfloat16_as_ushort(l1) << 16);
}

// ---------------- W prep (+ colmin init): fp32 -> swizzled bf16 hi/lo + ||w||^2 ----------------
__global__ void prep_kernel(const float* __restrict__ W) {
    const int tile = blockIdx.x;             // 0..7
    const int tid = threadIdx.x;
    const int wid = tid >> 5;                // 8 warps x 8 rows
    const int lane = tid & 31;
    if (tile == 0) {                          // init colmin (rowmin is plain-stored)
        g_colmin[tid]       = 0x7F800000;
        g_colmin[tid + 256] = 0x7F800000;
    }
    float2 v[8];
#pragma unroll
    for (int r = 0; r < 8; r++) {
        int rl = wid * 8 + r;
        v[r] = *(const float2*)(W + (size_t)(tile * TN + rl) * DDIM + 2 * lane);
    }
#pragma unroll
    for (int r = 0; r < 8; r++) {
        int rl = wid * 8 + r;
        float ss = warp_red_sum32(v[r].x * v[r].x + v[r].y * v[r].y);
        if (lane == 0) g_w2[tile * TN + rl] = ss;
        uint32_t hp, lp;
        split_bf16(v[r].x, v[r].y, hp, lp);
        uint32_t off = (uint32_t)tile * 8192u + swz((uint32_t)(rl * 128 + lane * 4));
        *(uint32_t*)(g_whi + off) = hp;
        *(uint32_t*)(g_wlo + off) = lp;
    }
}

// ---------------- fused normalize + split-bf16 GEMM + distance-min ----------------
__global__ void __launch_bounds__(256, 3)
fused_kernel(const float* __restrict__ x, float* __restrict__ out) {
    extern __shared__ char smem[];
    const int tid  = threadIdx.x;
    const int wid  = tid >> 5;
    const int lane = tid & 31;
    const int m0   = blockIdx.x * TM;
    const uint32_t sb = smem_u32(smem);

    int*   rowmin_s = (int*)(smem + OFF_RMIN);
    int*   colmin_s = (int*)(smem + OFF_CMIN);
    float* w2s      = (float*)(smem + OFF_W2);

    // init smem scratch + load w2
    if (tid < 128) rowmin_s[tid] = 0x7F800000;
#pragma unroll
    for (int i = tid; i < KPROT; i += 256) {
        colmin_s[i] = 0x7F800000;
        w2s[i] = g_w2[i];
    }

    // prefetch W tile 0 into buffer 0
    {
        uint32_t dst = sb + OFF_WB + (uint32_t)tid * 16;
        cp16(dst,         g_whi + tid * 16);
        cp16(dst + 4096,  g_whi + 4096 + tid * 16);
        cp16(dst + 8192,  g_wlo + tid * 16);
        cp16(dst + 12288, g_wlo + 4096 + tid * 16);
        cp_commit();
    }

    // ---- A: load, normalize, write xn twice, split to swizzled bf16 hi/lo ----
    {
        float2 v[16];
        const float* xb = x + (size_t)(m0 + wid * 16) * DDIM + 2 * lane;
#pragma unroll
        for (int r = 0; r < 16; r++) v[r] = *(const float2*)(xb + r * DDIM);
        float* o0 = out + (size_t)(m0 + wid * 16) * DDIM + 2 * lane;
        float* o1 = o0 + XN1_OFF;
#pragma unroll
        for (int r = 0; r < 16; r++) {
            float ss = warp_red_sum32(v[r].x * v[r].x + v[r].y * v[r].y);
            float sc = 1.0f / fmaxf(sqrtf(ss), 1e-12f);
            float a0 = v[r].x * sc, a1 = v[r].y * sc;
            *(float2*)(o0 + r * DDIM) = make_float2(a0, a1);
            *(float2*)(o1 + r * DDIM) = make_float2(a0, a1);
            uint32_t hp, lp;
            split_bf16(a0, a1, hp, lp);
            uint32_t sw = swz((uint32_t)((wid * 16 + r) * 128 + lane * 4));
            *(uint32_t*)(smem + OFF_AHI + sw) = hp;
            *(uint32_t*)(smem + OFF_ALO + sw) = lp;
        }
    }

    // warp layout: 4(M) x 2(N); warp tile 32(M) x 32(N)
    const int wm = wid & 3;              // 0..3 -> M rows [wm*32, +32)
    const int wn = wid >> 2;             // 0..1 -> N cols [wn*32, +32)
    const int rr = lane >> 2;            // acc row within 8
    const int cc = (lane & 3) * 2;       // acc col pair

    // ldmatrix lane address components (x4 for both A and B)
    const uint32_t a_row  = (uint32_t)(wm * 32 + (lane & 7) + ((lane >> 3) & 1) * 8);
    const uint32_t a_kb   = (uint32_t)(((lane >> 4) & 1) * 16);
    const uint32_t b_row  = (uint32_t)(wn * 32 + (lane & 7) + ((lane >> 4) & 1) * 8);
    const uint32_t b_kb   = (uint32_t)(((lane >> 3) & 1) * 16);

    float rm[4];
#pragma unroll
    for (int s = 0; s < 4; s++) rm[s] = __int_as_float(0x7F800000);

    float* proto = out + PROTO_OFF;

    for (int t = 0; t < NTILES; t++) {
        cp_wait<0>();        // W tile t data has arrived
        __syncthreads();     // publish tile t; prove tile t-1 buffer drained
        if (t < NTILES - 1) {  // prefetch t+1 into the drained buffer (overlaps compute)
            uint32_t dst = sb + OFF_WB + (uint32_t)(((t + 1) & 1) * 16384) + (uint32_t)tid * 16;
            const unsigned char* sh = g_whi + (t + 1) * 8192 + tid * 16;
            const unsigned char* sl = g_wlo + (t + 1) * 8192 + tid * 16;
            cp16(dst, sh); cp16(dst + 4096, sh + 4096);
            cp16(dst + 8192, sl); cp16(dst + 12288, sl + 4096);
            cp_commit();
        }

        const uint32_t wb = sb + OFF_WB + (uint32_t)((t & 1) * 16384);

        float acc[2][4][4];
#pragma unroll
        for (int mb = 0; mb < 2; mb++)
#pragma unroll
            for (int nf = 0; nf < 4; nf++)
#pragma unroll
                for (int c = 0; c < 4; c++) acc[mb][nf][c] = 0.0f;

#pragma unroll
        for (int ks = 0; ks < 4; ks++) {
            const uint32_t koff = (uint32_t)(ks * 32);
            // B fragments: hi and lo, each 2 x ldsm_x4 (n16 x k16 per load)
            uint32_t bh[2][4], bl[2][4];
#pragma unroll
            for (int nb = 0; nb < 2; nb++) {
                uint32_t baddr = swz(((b_row + nb * 16) << 7) + koff + b_kb);
                ldsm_x4(bh[nb][0], bh[nb][1], bh[nb][2], bh[nb][3], wb + baddr);
                ldsm_x4(bl[nb][0], bl[nb][1], bl[nb][2], bl[nb][3], wb + 8192u + baddr);
            }
#pragma unroll
            for (int mb = 0; mb < 2; mb++) {
                uint32_t aaddr = swz(((a_row + mb * 16) << 7) + koff + a_kb);
                uint32_t ah0, ah1, ah2, ah3, al0, al1, al2, al3;
                ldsm_x4(ah0, ah1, ah2, ah3, sb + OFF_AHI + aaddr);
                ldsm_x4(al0, al1, al2, al3, sb + OFF_ALO + aaddr);
#pragma unroll
                for (int nb = 0; nb < 2; nb++) {
                    // hi x hi
                    mma16816(acc[mb][nb*2][0],   acc[mb][nb*2][1],   acc[mb][nb*2][2],   acc[mb][nb*2][3],
                             ah0, ah1, ah2, ah3, bh[nb][0], bh[nb][1]);
                    mma16816(acc[mb][nb*2+1][0], acc[mb][nb*2+1][1], acc[mb][nb*2+1][2], acc[mb][nb*2+1][3],
                             ah0, ah1, ah2, ah3, bh[nb][2], bh[nb][3]);
                    // hi x lo
                    mma16816(acc[mb][nb*2][0],   acc[mb][nb*2][1],   acc[mb][nb*2][2],   acc[mb][nb*2][3],
                             ah0, ah1, ah2, ah3, bl[nb][0], bl[nb][1]);
                    mma16816(acc[mb][nb*2+1][0], acc[mb][nb*2+1][1], acc[mb][nb*2+1][2], acc[mb][nb*2+1][3],
                             ah0, ah1, ah2, ah3, bl[nb][2], bl[nb][3]);
                    // lo x hi
                    mma16816(acc[mb][nb*2][0],   acc[mb][nb*2][1],   acc[mb][nb*2][2],   acc[mb][nb*2][3],
                             al0, al1, al2, al3, bh[nb][0], bh[nb][1]);
                    mma16816(acc[mb][nb*2+1][0], acc[mb][nb*2+1][1], acc[mb][nb*2+1][2], acc[mb][nb*2+1][3],
                             al0, al1, al2, al3, bh[nb][2], bh[nb][3]);
                }
            }
        }

        // ---- proto store directly from accumulators ----
#pragma unroll
        for (int mb = 0; mb < 2; mb++) {
            size_t rowg = (size_t)(m0 + wm * 32 + mb * 16 + rr);
            float* base = proto + rowg * KPROT + t * TN + wn * 32 + cc;
#pragma unroll
            for (int nf = 0; nf < 4; nf++) {
                *(float2*)(base + nf * 8)             = make_float2(acc[mb][nf][0], acc[mb][nf][1]);
                *(float2*)(base + nf * 8 + 8 * KPROT) = make_float2(acc[mb][nf][2], acc[mb][nf][3]);
            }
        }

        // ---- distance mins ----
#pragma unroll
        for (int nf = 0; nf < 4; nf++) {
            int colg = t * TN + wn * 32 + nf * 8 + cc;
            float w0 = 1.0f + w2s[colg];
            float w1 = 1.0f + w2s[colg + 1];
            float cm0 = __int_as_float(0x7F800000);
            float cm1 = cm0;
#pragma unroll
            for (int mb = 0; mb < 2; mb++) {
                float s0 = fmaf(-2.0f, acc[mb][nf][0], w0);
                float s1 = fmaf(-2.0f, acc[mb][nf][1], w1);
                float s2 = fmaf(-2.0f, acc[mb][nf][2], w0);
                float s3 = fmaf(-2.0f, acc[mb][nf][3], w1);
                rm[mb * 2]     = fminf(rm[mb * 2],     fminf(s0, s1));
                rm[mb * 2 + 1] = fminf(rm[mb * 2 + 1], fminf(s2, s3));
                cm0 = fminf(cm0, fminf(s0, s2));
                cm1 = fminf(cm1, fminf(s1, s3));
            }
            cm0 = fminf(cm0, __shfl_xor_sync(0xFFFFFFFFu, cm0, 4));
            cm0 = fminf(cm0, __shfl_xor_sync(0xFFFFFFFFu, cm0, 8));
            cm0 = fminf(cm0, __shfl_xor_sync(0xFFFFFFFFu, cm0, 16));
            cm1 = fminf(cm1, __shfl_xor_sync(0xFFFFFFFFu, cm1, 4));
            cm1 = fminf(cm1, __shfl_xor_sync(0xFFFFFFFFu, cm1, 8));
            cm1 = fminf(cm1, __shfl_xor_sync(0xFFFFFFFFu, cm1, 16));
            if (lane < 4) {
                atomicMin(&colmin_s[colg],     __float_as_int(fmaxf(cm0, 1e-12f)));
                atomicMin(&colmin_s[colg + 1], __float_as_int(fmaxf(cm1, 1e-12f)));
            }
        }
    }

    // ---- finalize row mins (register -> lane reduce -> smem -> global store) ----
#pragma unroll
    for (int s = 0; s < 4; s++) {
        rm[s] = fminf(rm[s], __shfl_xor_sync(0xFFFFFFFFu, rm[s], 1));
        rm[s] = fminf(rm[s], __shfl_xor_sync(0xFFFFFFFFu, rm[s], 2));
    }
    if ((lane & 3) == 0) {
#pragma unroll
        for (int s = 0; s < 4; s++) {
            int rl = wm * 32 + (s >> 1) * 16 + rr + (s & 1) * 8;
            atomicMin(&rowmin_s[rl], __float_as_int(fmaxf(rm[s], 1e-12f)));
        }
    }
    __syncthreads();
    if (tid < 128) g_rowmin[m0 + tid] = rowmin_s[tid];
#pragma unroll
    for (int i = tid; i < KPROT; i += 256)
        atomicMin(&g_colmin[i], colmin_s[i]);
}

// ---------------- deterministic reduction: stage 1 (row mins) ----------------
__global__ void rowred_kernel() {
    __shared__ float red[256];
    int tid = threadIdx.x;
    int base = blockIdx.x * 1024;
    float s = 0.0f;
#pragma unroll
    for (int j = 0; j < 4; j++) {
        int i = base + tid * 4 + j;
        s += sqrtf(fmaxf(__int_as_float(g_rowmin[i]), 1e-12f));
    }
    red[tid] = s;
    __syncthreads();
    for (int st = 128; st > 0; st >>= 1) { if (tid < st) red[tid] += red[tid + st]; __syncthreads(); }
    if (tid == 0) g_partial[blockIdx.x] = red[0];
}

// ---------------- finalize scalars ----------------
__global__ void finalize_kernel(const float* __restrict__ recon,
                                const float* __restrict__ kl,
                                const float* __restrict__ mmd,
                                float* __restrict__ outs) {
    __shared__ float red[256];
    int tid = threadIdx.x;

    float s = (tid < 128) ? g_partial[tid] : 0.0f;
    red[tid] = s;
    __syncthreads();
    for (int st = 128; st > 0; st >>= 1) { if (tid < st) red[tid] += red[tid + st]; __syncthreads(); }
    float rowsum = red[0];
    __syncthreads();

    float c = 0.0f;
#pragma unroll
    for (int j = 0; j < 2; j++) {
        int i = tid * 2 + j;
        c += sqrtf(fmaxf(__int_as_float(g_colmin[i]), 1e-12f));
    }
    red[tid] = c;
    __syncthreads();
    for (int st = 128; st > 0; st >>= 1) { if (tid < st) red[tid] += red[tid + st]; __syncthreads(); }

    if (tid == 0) {
        float colsum = red[0];
        outs[0] = recon[0] + 0.5f * kl[0] + mmd[0];
        outs[1] = 0.5f * (rowsum * (1.0f / (float)NROWS))
                + 0.5f * (colsum * (1.0f / (float)KPROT));
    }
}

extern "C" void kernel_launch(void* const* d_in, const int* in_sizes, int n_in,
                              void* d_out, int out_size) {
    const float* x     = (const float*)d_in[0];
    const float* W     = (const float*)d_in[1];
    const float* recon = (const float*)d_in[2];
    const float* kl    = (const float*)d_in[3];
    const float* mmd   = (const float*)d_in[4];
    float* out = (float*)d_out;
    (void)in_sizes; (void)n_in; (void)out_size;

    cudaFuncSetAttribute(fused_kernel, cudaFuncAttributeMaxDynamicSharedMemorySize, SMEM_TOTAL);

    prep_kernel<<<NTILES, 256>>>(W);
    fused_kernel<<<NROWS / TM, 256, SMEM_TOTAL>>>(x, out);
    rowred_kernel<<<128, 256>>>();
    finalize_kernel<<<1, 256>>>(recon, kl, mmd, out + SCAL_OFF);
}